// round 3
// baseline (speedup 1.0000x reference)
#include <cuda_runtime.h>
#include <math.h>

#define B 128
#define L 1024
#define P_TX 10.0f
#define P_NOISE 6.2946e-14f

// One partial (sum of 8 R values) per row-block; 128 blocks per batch.
__device__ float g_bsum[B * L / 8];   // 16384 floats

__inline__ __device__ float warp_reduce(float v) {
    #pragma unroll
    for (int o = 16; o; o >>= 1) v += __shfl_down_sync(0xffffffffu, v, o);
    return v;
}

// ---- Kernel 1: warp-per-row, Py computed inline from prob ----
// 8 warps/block = 8 consecutive rows, all in the same batch.
// Lane i loads 1 float4 of H and 2 float4 of prob (stride-2 y extraction).
__global__ void __launch_bounds__(256) row_kernel(const float* __restrict__ H,
                                                  const float* __restrict__ prob) {
    const int row  = blockIdx.x * 8 + (threadIdx.x >> 5);   // global row in [0, B*L)
    const int lane = threadIdx.x & 31;
    const int b    = row >> 10;
    const int k    = row & (L - 1);

    const float4* __restrict__ h4 = reinterpret_cast<const float4*>(H + (size_t)row * L);
    // prob slice for batch b: prob[2*b*L ... ], viewed as float4 (2 links per float4)
    const float4* __restrict__ p4 = reinterpret_cast<const float4*>(prob + 2 * (size_t)b * L);

    float acc = 0.0f;   // sum_j H[k,j]^2 * y[j]   (P folded in at epilogue)
    #pragma unroll
    for (int i = 0; i < 8; i++) {
        const int t = i * 32 + lane;          // float4 index within the row
        float4 h  = __ldg(h4 + t);
        float4 pa = __ldg(p4 + 2 * t);        // y[4t]   = pa.y, y[4t+1] = pa.w
        float4 pb = __ldg(p4 + 2 * t + 1);    // y[4t+2] = pb.y, y[4t+3] = pb.w
        acc = fmaf(h.x * h.x, pa.y, acc);
        acc = fmaf(h.y * h.y, pa.w, acc);
        acc = fmaf(h.z * h.z, pb.y, acc);
        acc = fmaf(h.w * h.w, pb.w, acc);
    }

    acc = warp_reduce(acc);

    __shared__ float sR[8];
    if (lane == 0) {
        float d      = __ldg(H + (size_t)row * L + k);            // H[b,k,k] (L1 hot)
        float yk     = __ldg(prob + 2 * ((size_t)b * L + k) + 1); // y[k]
        float signal = P_TX * d * d * yk;
        float total  = P_TX * acc;
        float interf = total - signal;
        sR[threadIdx.x >> 5] =
            log1pf(signal / (interf + P_NOISE)) * 1.4426950408889634f;
    }
    __syncthreads();
    if (threadIdx.x == 0) {
        float s = 0.0f;
        #pragma unroll
        for (int w = 0; w < 8; w++) s += sR[w];
        g_bsum[blockIdx.x] = s;
    }
}

// ---- Kernel 2: reduce 128 partials per batch -> 1/sum, mean over batches ----
// One block, 1024 threads = 32 warps; each warp handles 4 batches.
__global__ void __launch_bounds__(1024) finalize_kernel(float* __restrict__ out) {
    const int wid  = threadIdx.x >> 5;
    const int lane = threadIdx.x & 31;

    float inv_acc = 0.0f;
    #pragma unroll
    for (int rep = 0; rep < 4; rep++) {
        const int bidx = wid * 4 + rep;   // batch index
        const float4* __restrict__ p =
            reinterpret_cast<const float4*>(g_bsum + bidx * 128);
        float4 v = p[lane];               // 32 lanes * 4 = 128 partials
        float s = (v.x + v.y) + (v.z + v.w);
        s = warp_reduce(s);
        if (lane == 0) inv_acc += 1.0f / s;
    }

    __shared__ float sm[32];
    if (lane == 0) sm[wid] = inv_acc;
    __syncthreads();
    if (wid == 0) {
        float v = sm[lane];
        v = warp_reduce(v);
        if (lane == 0) out[0] = v * (1.0f / (float)B);
    }
}

extern "C" void kernel_launch(void* const* d_in, const int* in_sizes, int n_in,
                              void* d_out, int out_size) {
    const float* prob = (const float*)d_in[0];
    const float* H    = (const float*)d_in[1];
    if (in_sizes[0] != 2 * B * L) { prob = (const float*)d_in[1]; H = (const float*)d_in[0]; }

    row_kernel<<<(B * L) / 8, 256>>>(H, prob);
    finalize_kernel<<<1, 1024>>>((float*)d_out);
}

// round 4
// speedup vs baseline: 1.6061x; 1.6061x over previous
#include <cuda_runtime.h>
#include <math.h>

#define B 128
#define L 1024
#define P_TX 10.0f
#define P_NOISE 6.2946e-14f

// One partial (sum of 8 R values) per row-block; 128 blocks per batch.
__device__ float g_bsum[B * L / 8];   // 16384 floats

__inline__ __device__ float warp_reduce(float v) {
    #pragma unroll
    for (int o = 16; o; o >>= 1) v += __shfl_down_sync(0xffffffffu, v, o);
    return v;
}

// ---- Kernel 1: warp-per-row; per-block smem staging of Py ----
// 8 warps/block = 8 consecutive rows, same batch b. Py staged to smem once.
__global__ void __launch_bounds__(256) row_kernel(const float* __restrict__ H,
                                                  const float* __restrict__ prob) {
    const int row  = blockIdx.x * 8 + (threadIdx.x >> 5);   // global row in [0, B*L)
    const int lane = threadIdx.x & 31;
    const int b    = blockIdx.x >> 7;                        // 128 blocks per batch
    const int k    = row & (L - 1);

    __shared__ float sPy[L];          // P * y[b, :]  (4 KB)

    // Cooperative stage: 256 threads x 4 elements, lane stride 8 B (2 lines/LDG)
    const float* __restrict__ pb = prob + 2 * (size_t)b * L;
    #pragma unroll
    for (int i = 0; i < 4; i++) {
        int j = i * 256 + threadIdx.x;
        sPy[j] = P_TX * __ldg(pb + 2 * j + 1);
    }
    __syncthreads();

    const float4* __restrict__ h4 = reinterpret_cast<const float4*>(H + (size_t)row * L);
    const float4* __restrict__ s4 = reinterpret_cast<const float4*>(sPy);

    float acc = 0.0f;
    #pragma unroll
    for (int i = 0; i < 8; i++) {
        const int t = i * 32 + lane;
        float4 h = __ldg(h4 + t);
        float4 p = s4[t];                       // conflict-free LDS.128
        acc = fmaf(h.x * h.x, p.x, acc);
        acc = fmaf(h.y * h.y, p.y, acc);
        acc = fmaf(h.z * h.z, p.z, acc);
        acc = fmaf(h.w * h.w, p.w, acc);
    }

    acc = warp_reduce(acc);

    __shared__ float sR[8];
    if (lane == 0) {
        float d      = __ldg(H + (size_t)row * L + k);   // H[b,k,k] (L1 hot)
        float signal = d * d * sPy[k];
        float interf = acc - signal;
        sR[threadIdx.x >> 5] =
            log1pf(signal / (interf + P_NOISE)) * 1.4426950408889634f;
    }
    __syncthreads();
    if (threadIdx.x == 0) {
        float s = 0.0f;
        #pragma unroll
        for (int w = 0; w < 8; w++) s += sR[w];
        g_bsum[blockIdx.x] = s;
    }
}

// ---- Kernel 2: reduce 128 partials per batch -> 1/sum, mean over batches ----
__global__ void __launch_bounds__(1024) finalize_kernel(float* __restrict__ out) {
    const int wid  = threadIdx.x >> 5;
    const int lane = threadIdx.x & 31;

    float inv_acc = 0.0f;
    #pragma unroll
    for (int rep = 0; rep < 4; rep++) {
        const int bidx = wid * 4 + rep;   // batch index
        const float4* __restrict__ p =
            reinterpret_cast<const float4*>(g_bsum + bidx * 128);
        float4 v = p[lane];               // 32 lanes * 4 = 128 partials
        float s = (v.x + v.y) + (v.z + v.w);
        s = warp_reduce(s);
        if (lane == 0) inv_acc += 1.0f / s;
    }

    __shared__ float sm[32];
    if (lane == 0) sm[wid] = inv_acc;
    __syncthreads();
    if (wid == 0) {
        float v = sm[lane];
        v = warp_reduce(v);
        if (lane == 0) out[0] = v * (1.0f / (float)B);
    }
}

extern "C" void kernel_launch(void* const* d_in, const int* in_sizes, int n_in,
                              void* d_out, int out_size) {
    const float* prob = (const float*)d_in[0];
    const float* H    = (const float*)d_in[1];
    if (in_sizes[0] != 2 * B * L) { prob = (const float*)d_in[1]; H = (const float*)d_in[0]; }

    row_kernel<<<(B * L) / 8, 256>>>(H, prob);
    finalize_kernel<<<1, 1024>>>((float*)d_out);
}